// round 3
// baseline (speedup 1.0000x reference)
#include <cuda_runtime.h>
#include <math.h>

#define NP 2048
#define IMG 128
#define NPIX (IMG*IMG)
#define TW 16
#define TH 8
#define RTHREADS 128

// Per-gaussian preprocessed data (unsorted then sorted copies).
__device__ float4 g_PA[NP], g_PB[NP], g_PBB[NP];
__device__ float  g_Pcb[NP], g_Pdepth[NP];
__device__ float4 g_SA[NP], g_SB[NP], g_SBB[NP];
__device__ float  g_Scb[NP];

__global__ void preprocess_kernel(const float* __restrict__ means,
                                  const float* __restrict__ feats,
                                  const float* __restrict__ ops,
                                  const float* __restrict__ scales,
                                  const float* __restrict__ rots,
                                  const float* __restrict__ V,
                                  const float* __restrict__ PM,
                                  float* __restrict__ out_radii)
{
    int i = blockIdx.x * blockDim.x + threadIdx.x;
    if (i >= NP) return;

    const float tanfov = 0.57735026918962576f;       // tan(FOV/2)
    const float fx = (float)IMG / (2.0f * tanfov);
    const float fy = fx;

    float mx = means[3*i], my = means[3*i+1], mz = means[3*i+2];

    // view transform
    float t0 = V[0]*mx + V[1]*my + V[2]*mz + V[3];
    float t1 = V[4]*mx + V[5]*my + V[6]*mz + V[7];
    float t2 = V[8]*mx + V[9]*my + V[10]*mz + V[11];
    float depth = t2;

    // projection
    float ph0 = PM[0]*mx + PM[1]*my + PM[2]*mz + PM[3];
    float ph1 = PM[4]*mx + PM[5]*my + PM[6]*mz + PM[7];
    float pw  = PM[12]*mx + PM[13]*my + PM[14]*mz + PM[15];
    float invpw = 1.0f / (pw + 1e-7f);
    float px = ((ph0*invpw + 1.0f) * (float)IMG - 1.0f) * 0.5f;
    float py = ((ph1*invpw + 1.0f) * (float)IMG - 1.0f) * 0.5f;

    // quaternion -> rotation
    float qw = rots[4*i], qx = rots[4*i+1], qy = rots[4*i+2], qz = rots[4*i+3];
    float qn = rsqrtf(qw*qw + qx*qx + qy*qy + qz*qz);
    qw *= qn; qx *= qn; qy *= qn; qz *= qn;
    float R00 = 1.0f - 2.0f*(qy*qy + qz*qz);
    float R01 = 2.0f*(qx*qy - qw*qz);
    float R02 = 2.0f*(qx*qz + qw*qy);
    float R10 = 2.0f*(qx*qy + qw*qz);
    float R11 = 1.0f - 2.0f*(qx*qx + qz*qz);
    float R12 = 2.0f*(qy*qz - qw*qx);
    float R20 = 2.0f*(qx*qz - qw*qy);
    float R21 = 2.0f*(qy*qz + qw*qx);
    float R22 = 1.0f - 2.0f*(qx*qx + qy*qy);

    float s0 = scales[3*i], s1 = scales[3*i+1], s2 = scales[3*i+2];
    float M00 = R00*s0, M01 = R01*s1, M02 = R02*s2;
    float M10 = R10*s0, M11 = R11*s1, M12 = R12*s2;
    float M20 = R20*s0, M21 = R21*s1, M22 = R22*s2;

    // sigma = M M^T (symmetric 3x3)
    float s00 = M00*M00 + M01*M01 + M02*M02;
    float s01 = M00*M10 + M01*M11 + M02*M12;
    float s02 = M00*M20 + M01*M21 + M02*M22;
    float s11 = M10*M10 + M11*M11 + M12*M12;
    float s12 = M10*M20 + M11*M21 + M12*M22;
    float s22 = M20*M20 + M21*M21 + M22*M22;

    // Jacobian of perspective projection
    float lim = 1.3f * tanfov;
    float invz = 1.0f / t2;
    float txc = fminf(fmaxf(t0*invz, -lim), lim) * t2;
    float tyc = fminf(fmaxf(t1*invz, -lim), lim) * t2;
    float J00 = fx*invz,  J02 = -fx*txc*invz*invz;
    float J11 = fy*invz,  J12 = -fy*tyc*invz*invz;

    float T00 = J00*V[0] + J02*V[8];
    float T01 = J00*V[1] + J02*V[9];
    float T02 = J00*V[2] + J02*V[10];
    float T10 = J11*V[4] + J12*V[8];
    float T11 = J11*V[5] + J12*V[9];
    float T12 = J11*V[6] + J12*V[10];

    // cov2d = T sigma T^T
    float u0 = s00*T00 + s01*T01 + s02*T02;
    float u1 = s01*T00 + s11*T01 + s12*T02;
    float u2 = s02*T00 + s12*T01 + s22*T02;
    float cov00 = T00*u0 + T01*u1 + T02*u2;
    float cov01 = T10*u0 + T11*u1 + T12*u2;
    float v0 = s00*T10 + s01*T11 + s02*T12;
    float v1 = s01*T10 + s11*T11 + s12*T12;
    float v2 = s02*T10 + s12*T11 + s22*T12;
    float cov11 = T10*v0 + T11*v1 + T12*v2;

    float a = cov00 + 0.3f;
    float b = cov01;
    float c = cov11 + 0.3f;
    float det = a*c - b*b;
    bool valid = (depth > 0.2f) && (det > 0.0f);
    float det_s = valid ? det : 1.0f;
    float invdet = 1.0f / det_s;
    float ca = c * invdet;
    float cbn = -b * invdet;
    float cc = a * invdet;

    float mid = 0.5f * (a + c);
    float lam = mid + sqrtf(fmaxf(mid*mid - det, 0.1f));
    float rad = valid ? ceilf(3.0f * sqrtf(lam)) : 0.0f;

    float op = ops[i];
    const float SH_C0 = 0.28209479177387814f;
    float cr  = fmaxf(SH_C0 * feats[3*i]   + 0.5f, 0.0f);
    float cg  = fmaxf(SH_C0 * feats[3*i+1] + 0.5f, 0.0f);
    float cbl = fmaxf(SH_C0 * feats[3*i+2] + 0.5f, 0.0f);

    // Exact cull bound: nonzero contribution requires op*exp(power) >= 1/255
    // with power <= 0; i.e. Q <= 2*ln(255*op). conic^{-1} = cov, so the
    // ellipse's axis-aligned extent is sqrt(2*tau*cov_ii).
    float tau = logf(255.0f * op) + 0.02f;   // small margin
    float dxm = sqrtf(fmaxf(2.0f * tau * a, 0.0f)) + 1.0f;
    float dym = sqrtf(fmaxf(2.0f * tau * c, 0.0f)) + 1.0f;

    float4 bb;
    if (valid) bb = make_float4(px - dxm, px + dxm, py - dym, py + dym);
    else       bb = make_float4(1e9f, -1e9f, 1e9f, -1e9f);

    g_PA[i]  = make_float4(px, py, ca, cbn);
    g_PB[i]  = make_float4(cc, op, cr, cg);
    g_Pcb[i] = cbl;
    g_PBB[i] = bb;
    g_Pdepth[i] = valid ? depth : __int_as_float(0x7f800000);  // +inf for invalid

    out_radii[i] = rad;
}

// Stable sort by (depth, idx) via bitonic sort of packed uint64 keys.
// Matches jnp.argsort's stable tie-breaking exactly.
__global__ void sort_kernel()
{
    __shared__ unsigned long long sk[NP];
    int tid = threadIdx.x;   // 1024 threads
    for (int i = tid; i < NP; i += 1024) {
        unsigned int bits = __float_as_uint(g_Pdepth[i]);  // positive floats: monotone
        sk[i] = ((unsigned long long)bits << 32) | (unsigned int)i;
    }
    __syncthreads();
    for (int k = 2; k <= NP; k <<= 1) {
        for (int j = k >> 1; j > 0; j >>= 1) {
            for (int i = tid; i < NP; i += 1024) {
                int l = i ^ j;
                if (l > i) {
                    unsigned long long va = sk[i], vb = sk[l];
                    bool asc = ((i & k) == 0);
                    if ((va > vb) == asc) { sk[i] = vb; sk[l] = va; }
                }
            }
            __syncthreads();
        }
    }
    // permute gaussian data into sorted order
    for (int i = tid; i < NP; i += 1024) {
        int o = (int)(sk[i] & 0xffffffffULL);
        g_SA[i]  = g_PA[o];
        g_SB[i]  = g_PB[o];
        g_SBB[i] = g_PBB[o];
        g_Scb[i] = g_Pcb[o];
    }
}

__global__ __launch_bounds__(RTHREADS)
void render_kernel(float* __restrict__ out)
{
    int tid = threadIdx.x;
    int tileX = blockIdx.x & 7;        // 8 tiles across (16 px each)
    int tileY = blockIdx.x >> 3;       // 16 tiles down (8 px each)
    int x0 = tileX * TW, y0 = tileY * TH;
    int lx = tid & 15, ly = tid >> 4;
    float gx = (float)(x0 + lx);
    float gy = (float)(y0 + ly);
    float tx0 = (float)x0, tx1 = (float)(x0 + TW - 1);
    float ty0 = (float)y0, ty1 = (float)(y0 + TH - 1);

    __shared__ float4 sA[RTHREADS], sB[RTHREADS];
    __shared__ float  sCb[RTHREADS];
    __shared__ int    wcnt[4];

    float T = 1.0f, C0 = 0.0f, C1 = 0.0f, C2 = 0.0f;
    const float ALPHA_MIN = 1.0f / 255.0f;

    for (int base = 0; base < NP; base += RTHREADS) {
        int i = base + tid;
        float4 bb = g_SBB[i];
        bool p = (bb.x <= tx1) && (bb.y >= tx0) && (bb.z <= ty1) && (bb.w >= ty0);

        unsigned m = __ballot_sync(0xffffffffu, p);
        int warp = tid >> 5, lane = tid & 31;
        if (lane == 0) wcnt[warp] = __popc(m);
        __syncthreads();
        int off = 0;
#pragma unroll
        for (int w = 0; w < 4; w++) off += (w < warp) ? wcnt[w] : 0;
        int cnt = wcnt[0] + wcnt[1] + wcnt[2] + wcnt[3];

        if (cnt > 0) {
            if (p) {
                int pos = off + __popc(m & ((1u << lane) - 1u));
                sA[pos]  = g_SA[i];
                sB[pos]  = g_SB[i];
                sCb[pos] = g_Scb[i];
            }
            __syncthreads();

            if (T > 1e-5f) {
                for (int j = 0; j < cnt; j++) {
                    float4 A = sA[j];
                    float4 B = sB[j];
                    float dx = gx - A.x, dy = gy - A.y;
                    // power = -0.5*(ca*dx^2 + cc*dy^2) - cb*dx*dy, pure FMA chain
                    float q = fmaf(A.z * dx, dx, B.x * dy * dy);
                    float power = fmaf(-0.5f, q, -A.w * dx * dy);
                    if (power > 0.0f) continue;
                    float alpha = fminf(0.99f, B.y * __expf(power));
                    if (alpha < ALPHA_MIN) continue;
                    float w = T * alpha;
                    C0 = fmaf(w, B.z, C0);
                    C1 = fmaf(w, B.w, C1);
                    C2 = fmaf(w, sCb[j], C2);
                    T *= (1.0f - alpha);
                }
            }
        }
        if (__syncthreads_count(T > 1e-5f) == 0) break;
    }

    int pix = (y0 + ly) * IMG + (x0 + lx);
    out[pix]          = C0 + T;
    out[NPIX + pix]   = C1 + T;
    out[2*NPIX + pix] = C2 + T;
}

extern "C" void kernel_launch(void* const* d_in, const int* in_sizes, int n_in,
                              void* d_out, int out_size)
{
    const float* means  = (const float*)d_in[0];
    // d_in[1] = means_2d (unused, zeros)
    const float* feats  = (const float*)d_in[2];
    const float* ops    = (const float*)d_in[3];
    const float* scales = (const float*)d_in[4];
    const float* rots   = (const float*)d_in[5];
    const float* V      = (const float*)d_in[6];
    const float* PM     = (const float*)d_in[7];
    // d_in[8] = campos (unused), d_in[9]/d_in[10] = H/W (fixed 128)

    float* out = (float*)d_out;
    float* out_radii = out + 3 * NPIX;

    preprocess_kernel<<<(NP + 255) / 256, 256>>>(means, feats, ops, scales, rots, V, PM, out_radii);
    sort_kernel<<<1, 1024>>>();
    render_kernel<<<128, RTHREADS>>>(out);
}

// round 5
// speedup vs baseline: 1.3976x; 1.3976x over previous
#include <cuda_runtime.h>
#include <math.h>

#define NP 2048
#define IMG 128
#define NPIX (IMG*IMG)
#define TW 16
#define TH 8
#define NTX 8
#define NTY 16
#define NTILES (NTX*NTY)
#define MWORDS 64              // 2048 bits / 32
#define RTHREADS 128
#define LISTCAP 128

// Per-gaussian preprocessed data (unsorted), then sorted copies.
__device__ float4 g_PA[NP], g_PB[NP], g_PBB[NP];
__device__ float  g_Pcb[NP], g_Pdepth[NP];
__device__ float4 g_SA[NP], g_SB[NP];
__device__ float  g_Scb[NP];
__device__ unsigned g_mask[NTILES * MWORDS];   // bit r set => sorted-rank-r gaussian touches tile

// ---------------------------------------------------------------------------
__global__ void preprocess_kernel(const float* __restrict__ means,
                                  const float* __restrict__ feats,
                                  const float* __restrict__ ops,
                                  const float* __restrict__ scales,
                                  const float* __restrict__ rots,
                                  const float* __restrict__ V,
                                  const float* __restrict__ PM,
                                  float* __restrict__ out_radii)
{
    int i = blockIdx.x * blockDim.x + threadIdx.x;
    if (i >= NP) return;

    // zero the tile masks (NTILES*MWORDS = 8192 words; 4 per thread)
    g_mask[i*4+0] = 0u; g_mask[i*4+1] = 0u; g_mask[i*4+2] = 0u; g_mask[i*4+3] = 0u;

    const float tanfov = 0.57735026918962576f;       // tan(FOV/2)
    const float fx = (float)IMG / (2.0f * tanfov);
    const float fy = fx;

    float mx = means[3*i], my = means[3*i+1], mz = means[3*i+2];

    // view transform
    float t0 = V[0]*mx + V[1]*my + V[2]*mz + V[3];
    float t1 = V[4]*mx + V[5]*my + V[6]*mz + V[7];
    float t2 = V[8]*mx + V[9]*my + V[10]*mz + V[11];
    float depth = t2;

    // projection
    float ph0 = PM[0]*mx + PM[1]*my + PM[2]*mz + PM[3];
    float ph1 = PM[4]*mx + PM[5]*my + PM[6]*mz + PM[7];
    float pw  = PM[12]*mx + PM[13]*my + PM[14]*mz + PM[15];
    float invpw = 1.0f / (pw + 1e-7f);
    float px = ((ph0*invpw + 1.0f) * (float)IMG - 1.0f) * 0.5f;
    float py = ((ph1*invpw + 1.0f) * (float)IMG - 1.0f) * 0.5f;

    // quaternion -> rotation
    float qw = rots[4*i], qx = rots[4*i+1], qy = rots[4*i+2], qz = rots[4*i+3];
    float qn = rsqrtf(qw*qw + qx*qx + qy*qy + qz*qz);
    qw *= qn; qx *= qn; qy *= qn; qz *= qn;
    float R00 = 1.0f - 2.0f*(qy*qy + qz*qz);
    float R01 = 2.0f*(qx*qy - qw*qz);
    float R02 = 2.0f*(qx*qz + qw*qy);
    float R10 = 2.0f*(qx*qy + qw*qz);
    float R11 = 1.0f - 2.0f*(qx*qx + qz*qz);
    float R12 = 2.0f*(qy*qz - qw*qx);
    float R20 = 2.0f*(qx*qz - qw*qy);
    float R21 = 2.0f*(qy*qz + qw*qx);
    float R22 = 1.0f - 2.0f*(qx*qx + qy*qy);

    float s0 = scales[3*i], s1 = scales[3*i+1], s2 = scales[3*i+2];
    float M00 = R00*s0, M01 = R01*s1, M02 = R02*s2;
    float M10 = R10*s0, M11 = R11*s1, M12 = R12*s2;
    float M20 = R20*s0, M21 = R21*s1, M22 = R22*s2;

    // sigma = M M^T
    float s00 = M00*M00 + M01*M01 + M02*M02;
    float s01 = M00*M10 + M01*M11 + M02*M12;
    float s02 = M00*M20 + M01*M21 + M02*M22;
    float s11 = M10*M10 + M11*M11 + M12*M12;
    float s12 = M10*M20 + M11*M21 + M12*M22;
    float s22 = M20*M20 + M21*M21 + M22*M22;

    // Jacobian
    float lim = 1.3f * tanfov;
    float invz = 1.0f / t2;
    float txc = fminf(fmaxf(t0*invz, -lim), lim) * t2;
    float tyc = fminf(fmaxf(t1*invz, -lim), lim) * t2;
    float J00 = fx*invz,  J02 = -fx*txc*invz*invz;
    float J11 = fy*invz,  J12 = -fy*tyc*invz*invz;

    float T00 = J00*V[0] + J02*V[8];
    float T01 = J00*V[1] + J02*V[9];
    float T02 = J00*V[2] + J02*V[10];
    float T10 = J11*V[4] + J12*V[8];
    float T11 = J11*V[5] + J12*V[9];
    float T12 = J11*V[6] + J12*V[10];

    // cov2d = T sigma T^T
    float u0 = s00*T00 + s01*T01 + s02*T02;
    float u1 = s01*T00 + s11*T01 + s12*T02;
    float u2 = s02*T00 + s12*T01 + s22*T02;
    float cov00 = T00*u0 + T01*u1 + T02*u2;
    float cov01 = T10*u0 + T11*u1 + T12*u2;
    float v0 = s00*T10 + s01*T11 + s02*T12;
    float v1 = s01*T10 + s11*T11 + s12*T12;
    float v2 = s02*T10 + s12*T11 + s22*T12;
    float cov11 = T10*v0 + T11*v1 + T12*v2;

    float a = cov00 + 0.3f;
    float b = cov01;
    float c = cov11 + 0.3f;
    float det = a*c - b*b;
    bool valid = (depth > 0.2f) && (det > 0.0f);
    float det_s = valid ? det : 1.0f;
    float invdet = 1.0f / det_s;
    float ca = c * invdet;
    float cbn = -b * invdet;
    float cc = a * invdet;

    float mid = 0.5f * (a + c);
    float lam = mid + sqrtf(fmaxf(mid*mid - det, 0.1f));
    float rad = valid ? ceilf(3.0f * sqrtf(lam)) : 0.0f;

    float op = ops[i];
    const float SH_C0 = 0.28209479177387814f;
    float cr  = fmaxf(SH_C0 * feats[3*i]   + 0.5f, 0.0f);
    float cg  = fmaxf(SH_C0 * feats[3*i+1] + 0.5f, 0.0f);
    float cbl = fmaxf(SH_C0 * feats[3*i+2] + 0.5f, 0.0f);

    // Exact cull bound: contribution nonzero iff Q <= 2*ln(255*op).
    // conic^{-1} = cov => axis-aligned extent sqrt(2*tau*cov_ii).
    float tau = logf(255.0f * op) + 0.02f;
    float dxm = sqrtf(fmaxf(2.0f * tau * a, 0.0f)) + 1.0f;
    float dym = sqrtf(fmaxf(2.0f * tau * c, 0.0f)) + 1.0f;

    float4 bb;
    if (valid) bb = make_float4(px - dxm, px + dxm, py - dym, py + dym);
    else       bb = make_float4(1e9f, -1e9f, 1e9f, -1e9f);

    g_PA[i]  = make_float4(px, py, ca, cbn);
    g_PB[i]  = make_float4(cc, op, cr, cg);
    g_Pcb[i] = cbl;
    g_PBB[i] = bb;
    g_Pdepth[i] = valid ? depth : __int_as_float(0x7f800000);

    out_radii[i] = rad;
}

// ---------------------------------------------------------------------------
// Rank sort (stable, exact argsort) + permute + tile-mask build.
// 256 blocks x 256 threads; warp w of block b owns element i = b*8 + w.
__global__ __launch_bounds__(256)
void rank_kernel()
{
    __shared__ unsigned long long sk[NP];

    int tid = threadIdx.x;
    int lane = tid & 31;
    int warp = tid >> 5;

    // load all keys into shared
    for (int i = tid; i < NP; i += 256) {
        unsigned bits = __float_as_uint(g_Pdepth[i]);     // positive floats: monotone
        sk[i] = ((unsigned long long)bits << 32) | (unsigned)i;
    }
    __syncthreads();

    int i = blockIdx.x * 8 + warp;
    unsigned long long mykey = sk[i];

    // count keys < mykey (lane-parallel, conflict-free stride)
    int cnt = 0;
    #pragma unroll 8
    for (int it = 0; it < NP / 32; it++) {
        cnt += (sk[lane + 32 * it] < mykey) ? 1 : 0;
    }
    int r = __reduce_add_sync(0xffffffffu, cnt);   // rank = sorted position

    if (lane == 0) {
        g_SA[r]  = g_PA[i];
        g_SB[r]  = g_PB[i];
        g_Scb[r] = g_Pcb[i];

        float4 bb = g_PBB[i];
        int txl = max(0,       (int)floorf(bb.x * (1.0f / TW)));
        int txh = min(NTX - 1, (int)floorf(bb.y * (1.0f / TW)));
        int tyl = max(0,       (int)floorf(bb.z * (1.0f / TH)));
        int tyh = min(NTY - 1, (int)floorf(bb.w * (1.0f / TH)));
        unsigned bit = 1u << (r & 31);
        int wofs = r >> 5;
        for (int ty = tyl; ty <= tyh; ty++)
            for (int tx = txl; tx <= txh; tx++)
                atomicOr(&g_mask[(ty * NTX + tx) * MWORDS + wofs], bit);
    }
}

// ---------------------------------------------------------------------------
__global__ __launch_bounds__(RTHREADS)
void render_kernel(float* __restrict__ out)
{
    int tid = threadIdx.x;
    int tile = blockIdx.x;
    int x0 = (tile & (NTX - 1)) * TW;
    int y0 = (tile >> 3) * TH;
    int lx = tid & 15, ly = tid >> 4;
    float gx = (float)(x0 + lx);
    float gy = (float)(y0 + ly);

    __shared__ unsigned smask[MWORDS];
    __shared__ int sofs[MWORDS + 1];          // exclusive prefix of popcounts
    __shared__ float4 lA[LISTCAP], lB[LISTCAP];
    __shared__ float  lCb[LISTCAP];

    if (tid < MWORDS) smask[tid] = g_mask[tile * MWORDS + tid];
    __syncthreads();

    // warp 0: prefix-scan the 64 popcounts
    if (tid < 32) {
        int c0 = __popc(smask[tid]);
        int c1 = __popc(smask[tid + 32]);
        int s0 = c0, s1 = c1;
        #pragma unroll
        for (int d = 1; d < 32; d <<= 1) {
            int t0 = __shfl_up_sync(0xffffffffu, s0, d);
            int t1 = __shfl_up_sync(0xffffffffu, s1, d);
            if (tid >= d) { s0 += t0; s1 += t1; }
        }
        int tot0 = __shfl_sync(0xffffffffu, s0, 31);
        sofs[tid]      = s0 - c0;                 // exclusive
        sofs[tid + 32] = tot0 + s1 - c1;
        if (tid == 31) sofs[64] = tot0 + s1;
    }
    __syncthreads();

    int total = sofs[MWORDS];
    float T = 1.0f, C0 = 0.0f, C1 = 0.0f, C2 = 0.0f;
    const float ALPHA_MIN = 1.0f / 255.0f;

    for (int base = 0; base < total; base += LISTCAP) {
        int idx = base + tid;
        if (idx < total) {
            // find word w with sofs[w] <= idx < sofs[w+1]  (binary search)
            int lo = 0, hi = MWORDS - 1;
            #pragma unroll
            for (int step = 0; step < 6; step++) {
                int mid = (lo + hi + 1) >> 1;
                if (sofs[mid] <= idx) lo = mid; else hi = mid - 1;
            }
            int w = lo;
            int k = idx - sofs[w];                // k-th set bit of word w
            unsigned mm = smask[w];
            int pos = 0;
            int c;
            c = __popc(mm & 0xFFFFu); if (k >= c) { k -= c; mm >>= 16; pos += 16; }
            c = __popc(mm & 0xFFu);   if (k >= c) { k -= c; mm >>= 8;  pos += 8; }
            c = __popc(mm & 0xFu);    if (k >= c) { k -= c; mm >>= 4;  pos += 4; }
            c = __popc(mm & 0x3u);    if (k >= c) { k -= c; mm >>= 2;  pos += 2; }
            c = __popc(mm & 0x1u);    if (k >= c) {         pos += 1; }
            int j = w * 32 + pos;                 // sorted rank
            lA[tid]  = g_SA[j];
            lB[tid]  = g_SB[j];
            lCb[tid] = g_Scb[j];
        }
        __syncthreads();

        int cnt = min(LISTCAP, total - base);
        if (T > 1e-5f) {
            for (int j = 0; j < cnt; j++) {
                float4 A = lA[j];
                float4 B = lB[j];
                float dx = gx - A.x, dy = gy - A.y;
                float q = fmaf(A.z * dx, dx, B.x * dy * dy);
                float power = fmaf(-0.5f, q, -A.w * dx * dy);
                if (power > 0.0f) continue;
                float alpha = fminf(0.99f, B.y * __expf(power));
                if (alpha < ALPHA_MIN) continue;
                float w = T * alpha;
                C0 = fmaf(w, B.z, C0);
                C1 = fmaf(w, B.w, C1);
                C2 = fmaf(w, lCb[j], C2);
                T *= (1.0f - alpha);
            }
        }
        if (base + LISTCAP < total) {
            if (__syncthreads_count(T > 1e-5f) == 0) break;
        }
    }

    int pix = (y0 + ly) * IMG + (x0 + lx);
    out[pix]          = C0 + T;
    out[NPIX + pix]   = C1 + T;
    out[2*NPIX + pix] = C2 + T;
}

// ---------------------------------------------------------------------------
extern "C" void kernel_launch(void* const* d_in, const int* in_sizes, int n_in,
                              void* d_out, int out_size)
{
    const float* means  = (const float*)d_in[0];
    const float* feats  = (const float*)d_in[2];
    const float* ops    = (const float*)d_in[3];
    const float* scales = (const float*)d_in[4];
    const float* rots   = (const float*)d_in[5];
    const float* V      = (const float*)d_in[6];
    const float* PM     = (const float*)d_in[7];

    float* out = (float*)d_out;
    float* out_radii = out + 3 * NPIX;

    preprocess_kernel<<<16, 128>>>(means, feats, ops, scales, rots, V, PM, out_radii);
    rank_kernel<<<256, 256>>>();
    render_kernel<<<NTILES, RTHREADS>>>(out);
}